// round 8
// baseline (speedup 1.0000x reference)
#include <cuda_runtime.h>
#include <cuda_bf16.h>
#include <cstdint>

#define NTOT 4096
#define FIN  128
#define FOUT 64
#define NH   4
#define NCOL 256           // NH*FOUT
#define NEG_INF -1.0e9f

// ---------------- scratch (device globals; no allocations) ----------------
__device__ float g_mask[(size_t)NTOT * NTOT];   // 64 MB
__device__ float g_P[NTOT * NCOL];              // proj, [n][h*64+o]
__device__ float g_S[NTOT * NCOL];              // skip, [n][c]
__device__ __nv_bfloat16 g_Bt[NH * FOUT * NTOT];// B^T bf16, [h][f][j]
__device__ float g_ssrc[NH * NTOT];
__device__ float g_stgt[NH * NTOT];
__device__ float g_cpart[32 * NH * NTOT];       // [rowtile][h][j]
__device__ float g_rpsum[32 * NTOT];            // [coltile][row]
__device__ float g_rpsq[32 * NTOT];
__device__ float g_mu[NTOT];
__device__ float g_rsig[NTOT];

// ---------------- helpers ----------------
__device__ __forceinline__ uint32_t smem_u32(const void* p) {
    uint32_t a;
    asm("{ .reg .u64 t; cvta.to.shared.u64 t, %1; cvt.u32.u64 %0, t; }" : "=r"(a) : "l"(p));
    return a;
}
#define SWZ(o) ((o) ^ (((o) >> 3) & 0x70))

__device__ __forceinline__ void ldm4(uint32_t* r, uint32_t addr) {
    asm volatile("ldmatrix.sync.aligned.m8n8.x4.shared.b16 {%0,%1,%2,%3}, [%4];"
                 : "=r"(r[0]), "=r"(r[1]), "=r"(r[2]), "=r"(r[3]) : "r"(addr));
}
__device__ __forceinline__ void mma16816(float* d, const uint32_t* a,
                                         uint32_t b0, uint32_t b1) {
    asm volatile("mma.sync.aligned.m16n8k16.row.col.f32.bf16.bf16.f32 "
                 "{%0,%1,%2,%3}, {%4,%5,%6,%7}, {%8,%9}, {%0,%1,%2,%3};"
                 : "+f"(d[0]), "+f"(d[1]), "+f"(d[2]), "+f"(d[3])
                 : "r"(a[0]), "r"(a[1]), "r"(a[2]), "r"(a[3]), "r"(b0), "r"(b1));
}
#define BAR_SYNC(id, cnt)   asm volatile("bar.sync %0, %1;"   :: "r"(id), "r"(cnt) : "memory")
#define BAR_ARRIVE(id, cnt) asm volatile("bar.arrive %0, %1;" :: "r"(id), "r"(cnt) : "memory")

// ---------------- K1: X @ [proj | skip^T] -> g_P, g_S ----------------
__global__ __launch_bounds__(256) void k_gemm1(const float* __restrict__ X,
                                               const float* __restrict__ Wp,
                                               const float* __restrict__ Wsk) {
    __shared__ float As[32 * 132];
    __shared__ float Ws[32 * 68];
    const int tid = threadIdx.x;
    const int bx = blockIdx.x, by = blockIdx.y;
    const int i0 = bx * 128;
    const int tr = tid >> 4;
    const int tc = tid & 15;

    float acc[8][4];
#pragma unroll
    for (int u = 0; u < 8; u++)
#pragma unroll
        for (int v = 0; v < 4; v++) acc[u][v] = 0.f;

    for (int s = 0; s < 4; s++) {
        const int k0 = s * 32;
        __syncthreads();
        {
            const int rl = tid >> 3;
            const int kl = (tid & 7) << 2;
#pragma unroll
            for (int p = 0; p < 4; p++) {
                const int r = rl + p * 32;
                float4 v = *(const float4*)(X + (i0 + r) * FIN + k0 + kl);
                As[(kl + 0) * 132 + r] = v.x;
                As[(kl + 1) * 132 + r] = v.y;
                As[(kl + 2) * 132 + r] = v.z;
                As[(kl + 3) * 132 + r] = v.w;
            }
        }
        if (by < 4) {
            const int kq = tid >> 4;
            const int c4 = (tid & 15) << 2;
#pragma unroll
            for (int p = 0; p < 2; p++) {
                const int kk = kq + p * 16;
                float4 v = *(const float4*)(Wp + by * (FIN * FOUT) + (k0 + kk) * FOUT + c4);
                *(float4*)(Ws + kk * 68 + c4) = v;
            }
        } else {
            const int kl = tid & 31;
            const int cg = tid >> 5;
            const int cb = (by - 4) * 64;
#pragma unroll
            for (int p = 0; p < 8; p++) {
                const int cc = cg * 8 + p;
                Ws[kl * 68 + cc] = Wsk[(cb + cc) * FIN + k0 + kl];
            }
        }
        __syncthreads();
#pragma unroll
        for (int k = 0; k < 32; k++) {
            float4 a0 = *(const float4*)(As + k * 132 + tr * 8);
            float4 a1 = *(const float4*)(As + k * 132 + tr * 8 + 4);
            float4 b  = *(const float4*)(Ws + k * 68 + tc * 4);
            float av[8] = {a0.x, a0.y, a0.z, a0.w, a1.x, a1.y, a1.z, a1.w};
            float bv[4] = {b.x, b.y, b.z, b.w};
#pragma unroll
            for (int u = 0; u < 8; u++)
#pragma unroll
                for (int v = 0; v < 4; v++) acc[u][v] += av[u] * bv[v];
        }
    }
    float* dst = (by < 4) ? g_P : g_S;
    const int cglob = (by & 3) * 64 + tc * 4;
#pragma unroll
    for (int u = 0; u < 8; u++) {
        const int row = i0 + tr * 8 + u;
        *(float4*)(dst + row * NCOL + cglob) =
            make_float4(acc[u][0], acc[u][1], acc[u][2], acc[u][3]);
    }
}

// ---------------- K1b: per-(h,n) scalar scores ----------------
__global__ void k_scores(const float* __restrict__ Wsrc, const float* __restrict__ Wtgt) {
    const int p = blockIdx.x * blockDim.x + threadIdx.x;
    const int n = p >> 2, h = p & 3;
    const float4* pr = (const float4*)(g_P + n * NCOL + h * FOUT);
    const float4* ws = (const float4*)(Wsrc + h * FOUT);
    const float4* wt = (const float4*)(Wtgt + h * FOUT);
    float ss = 0.f, st = 0.f;
#pragma unroll
    for (int o = 0; o < 16; o++) {
        float4 pv = pr[o], a = ws[o], b = wt[o];
        ss += pv.x * a.x + pv.y * a.y + pv.z * a.z + pv.w * a.w;
        st += pv.x * b.x + pv.y * b.y + pv.z * b.z + pv.w * b.w;
    }
    g_ssrc[h * NTOT + n] = ss;
    g_stgt[h * NTOT + n] = st;
}

// ---------------- K2: mask + colsum partials + row-stat partials ----------------
__device__ __forceinline__ float mask_val(float d, float b, float cut) {
    const float wdm = d + b;
    return (wdm > 0.f) ? wdm : ((b > cut) ? (b + wdm) : NEG_INF);
}

__global__ __launch_bounds__(256) void k_mask(const float* __restrict__ deg,
                                              const float* __restrict__ bond,
                                              const int* __restrict__ cutp) {
    __shared__ float Ssr[NH][128];
    __shared__ float Stg[NH][128];
    __shared__ float red[8][NH][128];
    const int tid = threadIdx.x;
    const int bx = blockIdx.x, by = blockIdx.y;
    const int j0 = bx * 128, i0 = by * 128;
    const float cut = (float)cutp[0];

    for (int idx = tid; idx < NH * 128; idx += 256) {
        const int h = idx >> 7, q = idx & 127;
        Ssr[h][q] = g_ssrc[h * NTOT + i0 + q];
        Stg[h][q] = g_stgt[h * NTOT + j0 + q];
    }
    __syncthreads();

    const int w = tid >> 5, l = tid & 31;
    float cs[NH][4];
#pragma unroll
    for (int h = 0; h < NH; h++)
#pragma unroll
        for (int u = 0; u < 4; u++) cs[h][u] = 0.f;
    float tg[NH][4];
#pragma unroll
    for (int h = 0; h < NH; h++)
#pragma unroll
        for (int u = 0; u < 4; u++) tg[h][u] = Stg[h][l * 4 + u];

    for (int rr = 0; rr < 16; rr++) {
        const int row = i0 + w * 16 + rr;
        const size_t base = (size_t)row * NTOT + j0 + l * 4;
        float4 d = *(const float4*)(deg + base);
        float4 b = *(const float4*)(bond + base);
        float m[4];
        m[0] = mask_val(d.x, b.x, cut);
        m[1] = mask_val(d.y, b.y, cut);
        m[2] = mask_val(d.z, b.z, cut);
        m[3] = mask_val(d.w, b.w, cut);
        *(float4*)(g_mask + base) = make_float4(m[0], m[1], m[2], m[3]);

        float rs = m[0] + m[1] + m[2] + m[3];
        float rq = m[0] * m[0] + m[1] * m[1] + m[2] * m[2] + m[3] * m[3];
#pragma unroll
        for (int off = 16; off > 0; off >>= 1) {
            rs += __shfl_xor_sync(0xffffffffu, rs, off);
            rq += __shfl_xor_sync(0xffffffffu, rq, off);
        }
        if (l == 0) { g_rpsum[bx * NTOT + row] = rs; g_rpsq[bx * NTOT + row] = rq; }

#pragma unroll
        for (int h = 0; h < NH; h++) {
            const float a = Ssr[h][w * 16 + rr];
#pragma unroll
            for (int u = 0; u < 4; u++) {
                float v = a + tg[h][u];
                v = fmaxf(v, 0.2f * v);
                cs[h][u] += __expf(m[u] + v);
            }
        }
    }
#pragma unroll
    for (int h = 0; h < NH; h++)
#pragma unroll
        for (int u = 0; u < 4; u++) red[w][h][l * 4 + u] = cs[h][u];
    __syncthreads();
    for (int o = tid; o < NH * 128; o += 256) {
        const int h = o >> 7, jj = o & 127;
        float s = 0.f;
#pragma unroll
        for (int ww = 0; ww < 8; ww++) s += red[ww][h][jj];
        g_cpart[(by * NH + h) * NTOT + j0 + jj] = s;
    }
}

// ---------------- K2b: parallel partial reduce + bf16 B^T production ----------------
__global__ __launch_bounds__(256) void k_finalize() {
    __shared__ float cinv_s[NH][16];
    __shared__ float red2[32];
    __shared__ float st[16][260];
    const int t = threadIdx.x;
    const int j0 = blockIdx.x * 16;

    {
        const int pair = t >> 2, sub = t & 3;
        const int hh = pair >> 4, jj = pair & 15;
        float c = 0.f;
#pragma unroll
        for (int p = 0; p < 8; p++)
            c += g_cpart[((sub * 8 + p) * NH + hh) * NTOT + j0 + jj];
        c += __shfl_xor_sync(0xffffffffu, c, 1);
        c += __shfl_xor_sync(0xffffffffu, c, 2);
        if (sub == 0) cinv_s[hh][jj] = 1.0f / c;
    }
    {
        const int j = (t >> 3) & 15, sub = t & 7;
        const float* src = (t < 128) ? g_rpsum : g_rpsq;
        float a = 0.f;
#pragma unroll
        for (int p = 0; p < 4; p++) a += src[(sub * 4 + p) * NTOT + j0 + j];
        a += __shfl_xor_sync(0xffffffffu, a, 1);
        a += __shfl_xor_sync(0xffffffffu, a, 2);
        a += __shfl_xor_sync(0xffffffffu, a, 4);
        if (sub == 0) red2[((t >> 7) << 4) + j] = a;
    }
    {
        const int jr = t >> 4, cg = (t & 15) * 16;
#pragma unroll
        for (int z = 0; z < 4; z++) {
            float4 v = *(const float4*)(g_P + (size_t)(j0 + jr) * NCOL + cg + z * 4);
            st[jr][cg + z * 4 + 0] = v.x;
            st[jr][cg + z * 4 + 1] = v.y;
            st[jr][cg + z * 4 + 2] = v.z;
            st[jr][cg + z * 4 + 3] = v.w;
        }
    }
    __syncthreads();
    if (t < 16) {
        const float mu = red2[t] * (1.0f / NTOT);
        const float var = red2[16 + t] * (1.0f / NTOT) - mu * mu;
        g_mu[j0 + t] = mu;
        g_rsig[j0 + t] = rsqrtf(fmaxf(var, 0.f) + 1e-5f);
    }
    {
        const int hh = t >> 6, f = t & 63;
        __nv_bfloat16 tmp[16];
#pragma unroll
        for (int z = 0; z < 16; z++)
            tmp[z] = __float2bfloat16(st[z][hh * 64 + f] * cinv_s[hh][z]);
        __nv_bfloat16* dst = g_Bt + ((size_t)hh * FOUT + f) * NTOT + j0;
        *(uint4*)(dst + 0) = *(uint4*)(tmp + 0);
        *(uint4*)(dst + 8) = *(uint4*)(tmp + 8);
    }
}

// ---------------- K3: warp-specialized HMMA GEMM ----------------
// grid (32,4), 512 threads. Warps 0-7 consumers (HMMA), warps 8-15 producers (E/B/LN).
// Double-buffered E (128x64 bf16 SW128) + B (64x64 bf16 SW128).
// Barriers: FULL[b] = bar.sync id 1+b (rendezvous, drains STS);
//           EMPTY[b] = consumers bar.arrive / producers bar.sync id 3+b.
#define OFF_TG   0
#define OFF_SSR  16384
#define OFF_MU   16896
#define OFF_RS   17408
#define OFF_EA   18432
#define OFF_BB   51200
#define SMEM_ATTN 67584

__global__ __launch_bounds__(512, 1) void k_attn(float* __restrict__ outY,
                                                 float* __restrict__ outLN) {
    extern __shared__ char sm[];
    const uint32_t smb = smem_u32(sm);
    const int tid = threadIdx.x;
    const int wid = tid >> 5;
    const int l = tid & 31;
    const int i0 = blockIdx.x * 128;
    const int h = blockIdx.y;

    float* tg_s  = (float*)(sm + OFF_TG);
    float* ssr_s = (float*)(sm + OFF_SSR);
    float* mu_s  = (float*)(sm + OFF_MU);
    float* rs_s  = (float*)(sm + OFF_RS);

#pragma unroll
    for (int p = 0; p < 8; p++) tg_s[tid + p * 512] = g_stgt[h * NTOT + tid + p * 512];
    if (tid < 128) {
        ssr_s[tid] = g_ssrc[h * NTOT + i0 + tid];
        mu_s[tid] = g_mu[i0 + tid];
        rs_s[tid] = g_rsig[i0 + tid];
    }
    __syncthreads();

    if (wid >= 8) {
        // ================= PRODUCER =================
        const int ptid = tid - 256;
        const int gr = ptid >> 4;          // 0..15
        const int gc = (ptid & 15) * 4;    // 0..60
        const int bf = ptid >> 2, bq = ptid & 3;

        float4 mv[8];
        uint4 bv0, bv1;
        // prefetch stage 0
#pragma unroll
        for (int p = 0; p < 8; p++)
            mv[p] = *(const float4*)(g_mask + (size_t)(i0 + gr + p * 16) * NTOT + gc);
        {
            const __nv_bfloat16* src = g_Bt + ((size_t)h * FOUT + bf) * NTOT + bq * 16;
            bv0 = *(const uint4*)(src);
            bv1 = *(const uint4*)(src + 8);
        }

        for (int kt = 0; kt < 64; kt++) {
            const int b = kt & 1;
            const int j0 = kt * 64;
            char* Ea = sm + OFF_EA + b * 16384;
            char* Bb = sm + OFF_BB + b * 8192;
            if (kt >= 2) BAR_SYNC(3 + b, 512);       // wait buffer freed

            *(uint4*)(Bb + SWZ(bf * 128 + bq * 32)) = bv0;
            *(uint4*)(Bb + SWZ(bf * 128 + bq * 32 + 16)) = bv1;

            const bool do_ln = ((kt >> 4) == h);
#pragma unroll
            for (int p = 0; p < 8; p++) {
                const int r = gr + p * 16;
                const float4 m4 = mv[p];
                if (do_ln) {
                    const float mu = mu_s[r], rg = rs_s[r];
                    *(float4*)(outLN + (size_t)(i0 + r) * NTOT + j0 + gc) =
                        make_float4((m4.x - mu) * rg, (m4.y - mu) * rg,
                                    (m4.z - mu) * rg, (m4.w - mu) * rg);
                }
                const float s = ssr_s[r];
                float4 tv = *(const float4*)(tg_s + j0 + gc);
                float v0 = s + tv.x; v0 = fmaxf(v0, 0.2f * v0);
                float v1 = s + tv.y; v1 = fmaxf(v1, 0.2f * v1);
                float v2 = s + tv.z; v2 = fmaxf(v2, 0.2f * v2);
                float v3 = s + tv.w; v3 = fmaxf(v3, 0.2f * v3);
                const float e0 = __expf(m4.x + v0);
                const float e1 = __expf(m4.y + v1);
                const float e2 = __expf(m4.z + v2);
                const float e3 = __expf(m4.w + v3);
                __nv_bfloat162 h01 = __floats2bfloat162_rn(e0, e1);
                __nv_bfloat162 h23 = __floats2bfloat162_rn(e2, e3);
                uint2 pk;
                pk.x = *(uint32_t*)&h01;
                pk.y = *(uint32_t*)&h23;
                *(uint2*)(Ea + SWZ(r * 128 + gc * 2)) = pk;
            }

            // prefetch next stage before the rendezvous (LDGs fly across it)
            if (kt < 63) {
                const int j1 = j0 + 64;
#pragma unroll
                for (int p = 0; p < 8; p++)
                    mv[p] = *(const float4*)(g_mask + (size_t)(i0 + gr + p * 16) * NTOT + j1 + gc);
                const __nv_bfloat16* src = g_Bt + ((size_t)h * FOUT + bf) * NTOT + j1 + bq * 16;
                bv0 = *(const uint4*)(src);
                bv1 = *(const uint4*)(src + 8);
            }
            BAR_SYNC(1 + b, 512);                    // publish (drains STS)
        }
    } else {
        // ================= CONSUMER =================
        const int quad = l >> 3, lr = l & 7;
        const int kc0 = (quad >> 1) * 8;
        uint32_t offA[2][4], offB[2][4];
        {
            const int ar = (wid & 3) * 32 + (quad & 1) * 8 + lr;
            const int br = (wid >> 2) * 32 + (quad & 1) * 8 + lr;
#pragma unroll
            for (int mt = 0; mt < 2; mt++)
#pragma unroll
                for (int kc = 0; kc < 4; kc++)
                    offA[mt][kc] = SWZ((ar + mt * 16) * 128 + (kc0 + kc * 16) * 2);
#pragma unroll
            for (int nt = 0; nt < 2; nt++)
#pragma unroll
                for (int kc = 0; kc < 4; kc++)
                    offB[nt][kc] = SWZ((br + nt * 16) * 128 + (kc0 + kc * 16) * 2);
        }

        float acc[2][4][4];
#pragma unroll
        for (int mt = 0; mt < 2; mt++)
#pragma unroll
            for (int nt = 0; nt < 4; nt++)
#pragma unroll
                for (int z = 0; z < 4; z++) acc[mt][nt][z] = 0.f;

        for (int kt = 0; kt < 64; kt++) {
            const int b = kt & 1;
            BAR_SYNC(1 + b, 512);                    // wait FULL
            const uint32_t ea = smb + OFF_EA + b * 16384;
            const uint32_t bb = smb + OFF_BB + b * 8192;
#pragma unroll
            for (int kc = 0; kc < 4; kc++) {
                uint32_t af0[4], af1[4], bf0[4], bf1[4];
                ldm4(af0, ea + offA[0][kc]);
                ldm4(af1, ea + offA[1][kc]);
                ldm4(bf0, bb + offB[0][kc]);
                ldm4(bf1, bb + offB[1][kc]);
                mma16816(acc[0][0], af0, bf0[0], bf0[2]);
                mma16816(acc[0][1], af0, bf0[1], bf0[3]);
                mma16816(acc[0][2], af0, bf1[0], bf1[2]);
                mma16816(acc[0][3], af0, bf1[1], bf1[3]);
                mma16816(acc[1][0], af1, bf0[0], bf0[2]);
                mma16816(acc[1][1], af1, bf0[1], bf0[3]);
                mma16816(acc[1][2], af1, bf1[0], bf1[2]);
                mma16816(acc[1][3], af1, bf1[1], bf1[3]);
            }
            BAR_ARRIVE(3 + b, 512);                  // free buffer
        }

        // epilogue: + skip, ELU, store
        const int groupr = l >> 2;
        const int cq = (l & 3) * 2;
#pragma unroll
        for (int mt = 0; mt < 2; mt++) {
#pragma unroll
            for (int half = 0; half < 2; half++) {
                const int row = i0 + (wid & 3) * 32 + mt * 16 + groupr + half * 8;
#pragma unroll
                for (int nt = 0; nt < 4; nt++) {
                    const int col = h * 64 + (wid >> 2) * 32 + nt * 8 + cq;
                    const float2 sk = *(const float2*)(g_S + (size_t)row * NCOL + col);
                    float vx = acc[mt][nt][half * 2 + 0] + sk.x;
                    float vy = acc[mt][nt][half * 2 + 1] + sk.y;
                    float2 o;
                    o.x = vx > 0.f ? vx : expm1f(vx);
                    o.y = vy > 0.f ? vy : expm1f(vy);
                    *(float2*)(outY + (size_t)row * NCOL + col) = o;
                }
            }
        }
    }
}

// ---------------- launch ----------------
extern "C" void kernel_launch(void* const* d_in, const int* in_sizes, int n_in,
                              void* d_out, int out_size) {
    const float* x    = (const float*)d_in[0];
    const float* deg  = (const float*)d_in[1];
    const float* bond = (const float*)d_in[3];
    const float* wp   = (const float*)d_in[4];
    const float* wsrc = (const float*)d_in[5];
    const float* wtgt = (const float*)d_in[6];
    const float* wsk  = (const float*)d_in[7];
    const int*   cutp = (const int*)d_in[8];

    float* outY  = (float*)d_out;
    float* outLN = (float*)d_out + NTOT * NCOL;

    cudaFuncSetAttribute(k_attn, cudaFuncAttributeMaxDynamicSharedMemorySize, SMEM_ATTN);

    k_gemm1<<<dim3(32, 8), 256>>>(x, wp, wsk);
    k_scores<<<64, 256>>>(wsrc, wtgt);
    k_mask<<<dim3(32, 32), 256>>>(deg, bond, cutp);
    k_finalize<<<256, 256>>>();
    k_attn<<<dim3(32, 4), 512, SMEM_ATTN>>>(outY, outLN);
}

// round 9
// speedup vs baseline: 1.3181x; 1.3181x over previous
#include <cuda_runtime.h>
#include <cuda_bf16.h>
#include <cstdint>

#define NTOT 4096
#define FIN  128
#define FOUT 64
#define NH   4
#define NCOL 256           // NH*FOUT
#define NEG_INF -1.0e9f

// ---------------- scratch (device globals; no allocations) ----------------
__device__ float g_mask[(size_t)NTOT * NTOT];               // 64 MB
__device__ __nv_bfloat16 g_E[(size_t)NH * NTOT * NTOT];     // 128 MB, [h][i][j]
__device__ float g_P[NTOT * NCOL];                          // proj, [n][h*64+o]
__device__ float g_S[NTOT * NCOL];                          // skip, [n][c]
__device__ __nv_bfloat16 g_Bt[NH * FOUT * NTOT];            // B^T bf16, [h][f][j]
__device__ float g_ssrc[NH * NTOT];
__device__ float g_stgt[NH * NTOT];
__device__ float g_cpart[32 * NH * NTOT];                   // [rowtile][h][j]
__device__ float g_rpsum[32 * NTOT];                        // [coltile][row]
__device__ float g_rpsq[32 * NTOT];
__device__ float g_mu[NTOT];
__device__ float g_rsig[NTOT];

// ---------------- helpers ----------------
__device__ __forceinline__ uint32_t smem_u32(const void* p) {
    uint32_t a;
    asm("{ .reg .u64 t; cvta.to.shared.u64 t, %1; cvt.u32.u64 %0, t; }" : "=r"(a) : "l"(p));
    return a;
}
#define SWZ(o) ((o) ^ (((o) >> 3) & 0x70))

__device__ __forceinline__ void ldm4(uint32_t* r, uint32_t addr) {
    asm volatile("ldmatrix.sync.aligned.m8n8.x4.shared.b16 {%0,%1,%2,%3}, [%4];"
                 : "=r"(r[0]), "=r"(r[1]), "=r"(r[2]), "=r"(r[3]) : "r"(addr));
}
__device__ __forceinline__ void mma16816(float* d, const uint32_t* a,
                                         uint32_t b0, uint32_t b1) {
    asm volatile("mma.sync.aligned.m16n8k16.row.col.f32.bf16.bf16.f32 "
                 "{%0,%1,%2,%3}, {%4,%5,%6,%7}, {%8,%9}, {%0,%1,%2,%3};"
                 : "+f"(d[0]), "+f"(d[1]), "+f"(d[2]), "+f"(d[3])
                 : "r"(a[0]), "r"(a[1]), "r"(a[2]), "r"(a[3]), "r"(b0), "r"(b1));
}

// ---------------- K1: X @ [proj | skip^T] -> g_P, g_S ----------------
__global__ __launch_bounds__(256) void k_gemm1(const float* __restrict__ X,
                                               const float* __restrict__ Wp,
                                               const float* __restrict__ Wsk) {
    __shared__ float As[32 * 132];
    __shared__ float Ws[32 * 68];
    const int tid = threadIdx.x;
    const int bx = blockIdx.x, by = blockIdx.y;
    const int i0 = bx * 128;
    const int tr = tid >> 4;
    const int tc = tid & 15;

    float acc[8][4];
#pragma unroll
    for (int u = 0; u < 8; u++)
#pragma unroll
        for (int v = 0; v < 4; v++) acc[u][v] = 0.f;

    for (int s = 0; s < 4; s++) {
        const int k0 = s * 32;
        __syncthreads();
        {
            const int rl = tid >> 3;
            const int kl = (tid & 7) << 2;
#pragma unroll
            for (int p = 0; p < 4; p++) {
                const int r = rl + p * 32;
                float4 v = *(const float4*)(X + (i0 + r) * FIN + k0 + kl);
                As[(kl + 0) * 132 + r] = v.x;
                As[(kl + 1) * 132 + r] = v.y;
                As[(kl + 2) * 132 + r] = v.z;
                As[(kl + 3) * 132 + r] = v.w;
            }
        }
        if (by < 4) {
            const int kq = tid >> 4;
            const int c4 = (tid & 15) << 2;
#pragma unroll
            for (int p = 0; p < 2; p++) {
                const int kk = kq + p * 16;
                float4 v = *(const float4*)(Wp + by * (FIN * FOUT) + (k0 + kk) * FOUT + c4);
                *(float4*)(Ws + kk * 68 + c4) = v;
            }
        } else {
            const int kl = tid & 31;
            const int cg = tid >> 5;
            const int cb = (by - 4) * 64;
#pragma unroll
            for (int p = 0; p < 8; p++) {
                const int cc = cg * 8 + p;
                Ws[kl * 68 + cc] = Wsk[(cb + cc) * FIN + k0 + kl];
            }
        }
        __syncthreads();
#pragma unroll
        for (int k = 0; k < 32; k++) {
            float4 a0 = *(const float4*)(As + k * 132 + tr * 8);
            float4 a1 = *(const float4*)(As + k * 132 + tr * 8 + 4);
            float4 b  = *(const float4*)(Ws + k * 68 + tc * 4);
            float av[8] = {a0.x, a0.y, a0.z, a0.w, a1.x, a1.y, a1.z, a1.w};
            float bv[4] = {b.x, b.y, b.z, b.w};
#pragma unroll
            for (int u = 0; u < 8; u++)
#pragma unroll
                for (int v = 0; v < 4; v++) acc[u][v] += av[u] * bv[v];
        }
    }
    float* dst = (by < 4) ? g_P : g_S;
    const int cglob = (by & 3) * 64 + tc * 4;
#pragma unroll
    for (int u = 0; u < 8; u++) {
        const int row = i0 + tr * 8 + u;
        *(float4*)(dst + row * NCOL + cglob) =
            make_float4(acc[u][0], acc[u][1], acc[u][2], acc[u][3]);
    }
}

// ---------------- K1b: per-(h,n) scalar scores ----------------
__global__ void k_scores(const float* __restrict__ Wsrc, const float* __restrict__ Wtgt) {
    const int p = blockIdx.x * blockDim.x + threadIdx.x;
    const int n = p >> 2, h = p & 3;
    const float4* pr = (const float4*)(g_P + n * NCOL + h * FOUT);
    const float4* ws = (const float4*)(Wsrc + h * FOUT);
    const float4* wt = (const float4*)(Wtgt + h * FOUT);
    float ss = 0.f, st = 0.f;
#pragma unroll
    for (int o = 0; o < 16; o++) {
        float4 pv = pr[o], a = ws[o], b = wt[o];
        ss += pv.x * a.x + pv.y * a.y + pv.z * a.z + pv.w * a.w;
        st += pv.x * b.x + pv.y * b.y + pv.z * b.z + pv.w * b.w;
    }
    g_ssrc[h * NTOT + n] = ss;
    g_stgt[h * NTOT + n] = st;
}

// ---------------- K2: mask + E (bf16) + colsum partials + row-stat partials ----------------
__device__ __forceinline__ float mask_val(float d, float b, float cut) {
    const float wdm = d + b;
    return (wdm > 0.f) ? wdm : ((b > cut) ? (b + wdm) : NEG_INF);
}

__global__ __launch_bounds__(256) void k_mask(const float* __restrict__ deg,
                                              const float* __restrict__ bond,
                                              const int* __restrict__ cutp) {
    __shared__ float Ssr[NH][128];
    __shared__ float Stg[NH][128];
    __shared__ float red[8][NH][128];
    const int tid = threadIdx.x;
    const int bx = blockIdx.x, by = blockIdx.y;
    const int j0 = bx * 128, i0 = by * 128;
    const float cut = (float)cutp[0];

    for (int idx = tid; idx < NH * 128; idx += 256) {
        const int h = idx >> 7, q = idx & 127;
        Ssr[h][q] = g_ssrc[h * NTOT + i0 + q];
        Stg[h][q] = g_stgt[h * NTOT + j0 + q];
    }
    __syncthreads();

    const int w = tid >> 5, l = tid & 31;
    float cs[NH][4];
#pragma unroll
    for (int h = 0; h < NH; h++)
#pragma unroll
        for (int u = 0; u < 4; u++) cs[h][u] = 0.f;
    float tg[NH][4];
#pragma unroll
    for (int h = 0; h < NH; h++)
#pragma unroll
        for (int u = 0; u < 4; u++) tg[h][u] = Stg[h][l * 4 + u];

    for (int rr = 0; rr < 16; rr++) {
        const int row = i0 + w * 16 + rr;
        const size_t base = (size_t)row * NTOT + j0 + l * 4;
        float4 d = *(const float4*)(deg + base);
        float4 b = *(const float4*)(bond + base);
        float m[4];
        m[0] = mask_val(d.x, b.x, cut);
        m[1] = mask_val(d.y, b.y, cut);
        m[2] = mask_val(d.z, b.z, cut);
        m[3] = mask_val(d.w, b.w, cut);
        *(float4*)(g_mask + base) = make_float4(m[0], m[1], m[2], m[3]);

        float rs = m[0] + m[1] + m[2] + m[3];
        float rq = m[0] * m[0] + m[1] * m[1] + m[2] * m[2] + m[3] * m[3];
#pragma unroll
        for (int off = 16; off > 0; off >>= 1) {
            rs += __shfl_xor_sync(0xffffffffu, rs, off);
            rq += __shfl_xor_sync(0xffffffffu, rq, off);
        }
        if (l == 0) { g_rpsum[bx * NTOT + row] = rs; g_rpsq[bx * NTOT + row] = rq; }

#pragma unroll
        for (int h = 0; h < NH; h++) {
            const float a = Ssr[h][w * 16 + rr];
            float e[4];
#pragma unroll
            for (int u = 0; u < 4; u++) {
                float v = a + tg[h][u];
                v = fmaxf(v, 0.2f * v);
                e[u] = __expf(m[u] + v);
                cs[h][u] += e[u];
            }
            __nv_bfloat162 p0 = __floats2bfloat162_rn(e[0], e[1]);
            __nv_bfloat162 p1 = __floats2bfloat162_rn(e[2], e[3]);
            uint2 pk;
            pk.x = *(uint32_t*)&p0;
            pk.y = *(uint32_t*)&p1;
            *(uint2*)(g_E + (size_t)h * NTOT * NTOT + base) = pk;
        }
    }
#pragma unroll
    for (int h = 0; h < NH; h++)
#pragma unroll
        for (int u = 0; u < 4; u++) red[w][h][l * 4 + u] = cs[h][u];
    __syncthreads();
    for (int o = tid; o < NH * 128; o += 256) {
        const int h = o >> 7, jj = o & 127;
        float s = 0.f;
#pragma unroll
        for (int ww = 0; ww < 8; ww++) s += red[ww][h][jj];
        g_cpart[(by * NH + h) * NTOT + j0 + jj] = s;
    }
}

// ---------------- K2b: parallel partial reduce + bf16 B^T production ----------------
__global__ __launch_bounds__(256) void k_finalize() {
    __shared__ float cinv_s[NH][16];
    __shared__ float red2[32];
    __shared__ float st[16][260];
    const int t = threadIdx.x;
    const int j0 = blockIdx.x * 16;

    {
        const int pair = t >> 2, sub = t & 3;
        const int hh = pair >> 4, jj = pair & 15;
        float c = 0.f;
#pragma unroll
        for (int p = 0; p < 8; p++)
            c += g_cpart[((sub * 8 + p) * NH + hh) * NTOT + j0 + jj];
        c += __shfl_xor_sync(0xffffffffu, c, 1);
        c += __shfl_xor_sync(0xffffffffu, c, 2);
        if (sub == 0) cinv_s[hh][jj] = 1.0f / c;
    }
    {
        const int j = (t >> 3) & 15, sub = t & 7;
        const float* src = (t < 128) ? g_rpsum : g_rpsq;
        float a = 0.f;
#pragma unroll
        for (int p = 0; p < 4; p++) a += src[(sub * 4 + p) * NTOT + j0 + j];
        a += __shfl_xor_sync(0xffffffffu, a, 1);
        a += __shfl_xor_sync(0xffffffffu, a, 2);
        a += __shfl_xor_sync(0xffffffffu, a, 4);
        if (sub == 0) red2[((t >> 7) << 4) + j] = a;
    }
    {
        const int jr = t >> 4, cg = (t & 15) * 16;
#pragma unroll
        for (int z = 0; z < 4; z++) {
            float4 v = *(const float4*)(g_P + (size_t)(j0 + jr) * NCOL + cg + z * 4);
            st[jr][cg + z * 4 + 0] = v.x;
            st[jr][cg + z * 4 + 1] = v.y;
            st[jr][cg + z * 4 + 2] = v.z;
            st[jr][cg + z * 4 + 3] = v.w;
        }
    }
    __syncthreads();
    if (t < 16) {
        const float mu = red2[t] * (1.0f / NTOT);
        const float var = red2[16 + t] * (1.0f / NTOT) - mu * mu;
        g_mu[j0 + t] = mu;
        g_rsig[j0 + t] = rsqrtf(fmaxf(var, 0.f) + 1e-5f);
    }
    {
        const int hh = t >> 6, f = t & 63;
        __nv_bfloat16 tmp[16];
#pragma unroll
        for (int z = 0; z < 16; z++)
            tmp[z] = __float2bfloat16(st[z][hh * 64 + f] * cinv_s[hh][z]);
        __nv_bfloat16* dst = g_Bt + ((size_t)hh * FOUT + f) * NTOT + j0;
        *(uint4*)(dst + 0) = *(uint4*)(tmp + 0);
        *(uint4*)(dst + 8) = *(uint4*)(tmp + 8);
    }
}

// ---------------- K3: pure bf16 HMMA GEMM out = E @ B^T, fused LN + ELU ----------------
// grid (64, 4): bx = 64-row tile, by = head. K staged by 64 j, double buffered, 1 sync/stage.
// 8 warps: rb = wid&1 (32-row band), cb = wid>>1 (16-col band). ~33KB smem -> multi-CTA/SM.
__global__ __launch_bounds__(256, 2) void k_attn(float* __restrict__ outY,
                                                 float* __restrict__ outLN) {
    __shared__ __align__(1024) char Ebuf[2][8192];
    __shared__ __align__(1024) char Bbuf[2][8192];
    __shared__ float mu_s[64], rs_s[64];
    const int tid = threadIdx.x;
    const int wid = tid >> 5;
    const int l = tid & 31;
    const int i0 = blockIdx.x * 64;
    const int h = blockIdx.y;
    const __nv_bfloat16* Eh = g_E + (size_t)h * NTOT * NTOT;

    if (tid < 64) { mu_s[tid] = g_mu[i0 + tid]; rs_s[tid] = g_rsig[i0 + tid]; }

    // staging maps (E and B tiles are both 64 rows x 128B)
    const int er = tid >> 2, eq = tid & 3;          // row, 32B-group

    // ldmatrix offsets
    const int quad = l >> 3, lr = l & 7;
    const int rb = wid & 1, cb = wid >> 1;
    uint32_t offA[2][4], offB[4];
    {
        const int kc0 = (quad >> 1) * 8;
#pragma unroll
        for (int mt = 0; mt < 2; mt++)
#pragma unroll
            for (int kc = 0; kc < 4; kc++)
                offA[mt][kc] = SWZ((rb * 32 + mt * 16 + (quad & 1) * 8 + lr) * 128
                                   + (kc * 16 + kc0) * 2);
#pragma unroll
        for (int kc = 0; kc < 4; kc++)
            offB[kc] = SWZ((cb * 16 + (quad & 1) * 8 + lr) * 128 + (kc * 16 + kc0) * 2);
    }
    const uint32_t smbE = smem_u32(Ebuf);
    const uint32_t smbB = smem_u32(Bbuf);

    float acc[2][2][4];
#pragma unroll
    for (int mt = 0; mt < 2; mt++)
#pragma unroll
        for (int nt = 0; nt < 2; nt++)
#pragma unroll
            for (int z = 0; z < 4; z++) acc[mt][nt][z] = 0.f;

    // prefetch stage 0
    uint4 ev0, ev1, bv0, bv1;
    {
        const __nv_bfloat16* esrc = Eh + (size_t)(i0 + er) * NTOT + eq * 16;
        ev0 = *(const uint4*)(esrc);
        ev1 = *(const uint4*)(esrc + 8);
        const __nv_bfloat16* bsrc = g_Bt + ((size_t)h * FOUT + er) * NTOT + eq * 16;
        bv0 = *(const uint4*)(bsrc);
        bv1 = *(const uint4*)(bsrc + 8);
    }
    __syncthreads();   // mu_s/rs_s ready

    for (int kt = 0; kt < 64; kt++) {
        const int b = kt & 1;
        const int j0 = kt * 64;

        // store stage kt
        *(uint4*)(Ebuf[b] + SWZ(er * 128 + eq * 32)) = ev0;
        *(uint4*)(Ebuf[b] + SWZ(er * 128 + eq * 32 + 16)) = ev1;
        *(uint4*)(Bbuf[b] + SWZ(er * 128 + eq * 32)) = bv0;
        *(uint4*)(Bbuf[b] + SWZ(er * 128 + eq * 32 + 16)) = bv1;
        __syncthreads();

        // prefetch stage kt+1
        if (kt < 63) {
            const int j1 = j0 + 64;
            const __nv_bfloat16* esrc = Eh + (size_t)(i0 + er) * NTOT + j1 + eq * 16;
            ev0 = *(const uint4*)(esrc);
            ev1 = *(const uint4*)(esrc + 8);
            const __nv_bfloat16* bsrc = g_Bt + ((size_t)h * FOUT + er) * NTOT + j1 + eq * 16;
            bv0 = *(const uint4*)(bsrc);
            bv1 = *(const uint4*)(bsrc + 8);
        }

        // fused LN (this head's quarter of columns): mask -> (m-mu)*rsig
        if ((kt >> 4) == h) {
            const float mu = mu_s[er], rg = rs_s[er];
            const size_t base = (size_t)(i0 + er) * NTOT + j0 + eq * 16;
#pragma unroll
            for (int z = 0; z < 4; z++) {
                float4 m4 = *(const float4*)(g_mask + base + z * 4);
                *(float4*)(outLN + base + z * 4) =
                    make_float4((m4.x - mu) * rg, (m4.y - mu) * rg,
                                (m4.z - mu) * rg, (m4.w - mu) * rg);
            }
        }

        // HMMA on stage kt
        const uint32_t ea = smbE + b * 8192;
        const uint32_t bb = smbB + b * 8192;
#pragma unroll
        for (int kc = 0; kc < 4; kc++) {
            uint32_t af0[4], af1[4], bfr[4];
            ldm4(af0, ea + offA[0][kc]);
            ldm4(af1, ea + offA[1][kc]);
            ldm4(bfr, bb + offB[kc]);
            mma16816(acc[0][0], af0, bfr[0], bfr[2]);
            mma16816(acc[0][1], af0, bfr[1], bfr[3]);
            mma16816(acc[1][0], af1, bfr[0], bfr[2]);
            mma16816(acc[1][1], af1, bfr[1], bfr[3]);
        }
        __syncthreads();
    }

    // epilogue: + skip, ELU, store
    const int groupr = l >> 2;
    const int cq = (l & 3) * 2;
#pragma unroll
    for (int mt = 0; mt < 2; mt++) {
#pragma unroll
        for (int half = 0; half < 2; half++) {
            const int row = i0 + rb * 32 + mt * 16 + groupr + half * 8;
#pragma unroll
            for (int nt = 0; nt < 2; nt++) {
                const int col = h * 64 + cb * 16 + nt * 8 + cq;
                const float2 sk = *(const float2*)(g_S + (size_t)row * NCOL + col);
                float vx = acc[mt][nt][half * 2 + 0] + sk.x;
                float vy = acc[mt][nt][half * 2 + 1] + sk.y;
                float2 o;
                o.x = vx > 0.f ? vx : expm1f(vx);
                o.y = vy > 0.f ? vy : expm1f(vy);
                *(float2*)(outY + (size_t)row * NCOL + col) = o;
            }
        }
    }
}

// ---------------- launch ----------------
extern "C" void kernel_launch(void* const* d_in, const int* in_sizes, int n_in,
                              void* d_out, int out_size) {
    const float* x    = (const float*)d_in[0];
    const float* deg  = (const float*)d_in[1];
    const float* bond = (const float*)d_in[3];
    const float* wp   = (const float*)d_in[4];
    const float* wsrc = (const float*)d_in[5];
    const float* wtgt = (const float*)d_in[6];
    const float* wsk  = (const float*)d_in[7];
    const int*   cutp = (const int*)d_in[8];

    float* outY  = (float*)d_out;
    float* outLN = (float*)d_out + NTOT * NCOL;

    k_gemm1<<<dim3(32, 8), 256>>>(x, wp, wsk);
    k_scores<<<64, 256>>>(wsrc, wtgt);
    k_mask<<<dim3(32, 32), 256>>>(deg, bond, cutp);
    k_finalize<<<256, 256>>>();
    k_attn<<<dim3(64, 4), 256>>>(outY, outLN);
}